// round 15
// baseline (speedup 1.0000x reference)
#include <cuda_runtime.h>
#include <cuda_fp16.h>
#include <cstdint>
#include <math.h>

#define Nn 65536
#define Kc 8
#define Hs 128
#define Tt 4
#define APAD 136          // fp16 row stride (272B: conflict-free ldmatrix)
#define SPAD 136          // k_imma stage row stride in floats (544B)

// ---------------------------------------------------------------------------
// Device scratch (allocation-free rule: __device__ globals)
// ---------------------------------------------------------------------------
__device__ int   g_cnt[Tt];
__device__ int   g_perm[Tt][Nn];
__device__ float g_hsum[(size_t)Nn * Hs];
__device__ __align__(16) __half g_Bf[Tt][Hs * Hs];        // fp16 U_f
__device__ __align__(16) __half g_Bi[Tt][3][Hs * Hs];     // fp16 U_iou

// ---------------------------------------------------------------------------
// Helpers
// ---------------------------------------------------------------------------
__device__ __forceinline__ uint32_t smem_to_u32(const void* p) {
    uint32_t a;
    asm("{ .reg .u64 t; cvta.to.shared.u64 t, %1; cvt.u32.u64 %0, t; }" : "=r"(a) : "l"(p));
    return a;
}
__device__ __forceinline__ void ldm_x4(uint32_t* r, uint32_t a) {
    asm volatile("ldmatrix.sync.aligned.m8n8.x4.shared.b16 {%0,%1,%2,%3}, [%4];"
        : "=r"(r[0]), "=r"(r[1]), "=r"(r[2]), "=r"(r[3]) : "r"(a));
}
__device__ __forceinline__ void ldm_x4t(uint32_t* r, uint32_t a) {
    asm volatile("ldmatrix.sync.aligned.m8n8.x4.trans.shared.b16 {%0,%1,%2,%3}, [%4];"
        : "=r"(r[0]), "=r"(r[1]), "=r"(r[2]), "=r"(r[3]) : "r"(a));
}
__device__ __forceinline__ void mma16816h(float* c, const uint32_t* a, const uint32_t* b) {
    asm volatile("mma.sync.aligned.m16n8k16.row.col.f32.f16.f16.f32 "
        "{%0,%1,%2,%3}, {%4,%5,%6,%7}, {%8,%9}, {%0,%1,%2,%3};"
        : "+f"(c[0]), "+f"(c[1]), "+f"(c[2]), "+f"(c[3])
        : "r"(a[0]), "r"(a[1]), "r"(a[2]), "r"(a[3]), "r"(b[0]), "r"(b[1]));
}
__device__ __forceinline__ uint32_t f2h2(float x, float y) {
    uint32_t u;
    asm("cvt.rn.f16x2.f32 %0, %1, %2;" : "=r"(u) : "f"(y), "f"(x));
    return u;
}
__device__ __forceinline__ void f2h2_split(float x, float y, uint32_t& hi, uint32_t& lo) {
    hi = f2h2(x, y);
    __half2 h2 = *(__half2*)&hi;
    float bx = __low2float(h2), by = __high2float(h2);
    lo = f2h2(x - bx, y - by);
}
#define CP_ASYNC16(dst, src) \
    asm volatile("cp.async.cg.shared.global [%0], [%1], 16;" :: "r"(dst), "l"(src) : "memory")
#define CP_COMMIT()  asm volatile("cp.async.commit_group;" ::: "memory")
#define CP_WAIT0()   asm volatile("cp.async.wait_group 0;" ::: "memory")

// ---------------------------------------------------------------------------
// Bucket nodes by type
// ---------------------------------------------------------------------------
__global__ void k_zero() { if (threadIdx.x < Tt) g_cnt[threadIdx.x] = 0; }

__global__ void __launch_bounds__(256) k_bucket(const int* __restrict__ type_id) {
    __shared__ int scnt[Tt];
    __shared__ int sbase[Tt];
    const int tid = threadIdx.x;
    if (tid < Tt) scnt[tid] = 0;
    __syncthreads();
    const int n = blockIdx.x * 256 + tid;
    const int t = type_id[n];
    const int local = atomicAdd(&scnt[t], 1);
    __syncthreads();
    if (tid < Tt) sbase[tid] = atomicAdd(&g_cnt[tid], scnt[tid]);
    __syncthreads();
    g_perm[t][sbase[t] + local] = n;
}

// ---------------------------------------------------------------------------
// Weight prep: fp16 U_f and U_iou (row-major [i][j])
// ---------------------------------------------------------------------------
__global__ void __launch_bounds__(256) k_prepw(const float* __restrict__ U_iou,
                                               const float* __restrict__ U_f) {
    int idx = blockIdx.x * 256 + threadIdx.x;     // 262144
    int t   = idx >> 16;
    int rem = idx & 65535;
    int m   = rem >> 14;                          // 0 = f, 1..3 = iou jtile
    int i   = (rem >> 7) & 127;
    int j   = rem & 127;
    int e   = i * Hs + j;
    if (m == 0)
        g_Bf[t][e] = __float2half(U_f[((size_t)t * Hs + i) * Hs + j]);
    else
        g_Bi[t][m - 1][e] = __float2half(U_iou[((size_t)t * Hs + i) * 3 * Hs + (m - 1) * Hs + j]);
}

// ---------------------------------------------------------------------------
// k_fmma: PERSISTENT, cp.async h-prefetch, 2 CTAs/SM, grid = 4 x 74.
// A rows laid out CHILD-MAJOR: row = k*8 + nl. Warp grid 1(M) x 8(N):
// each warp owns all 64 rows x 16 cols (mt=0..3, nt=0..1). Fragment map puts
// node nl=lr's children k=2mt,2mt+1 in ONE thread's accumulators -> the
// 8-child sigmoid*c reduction is pure in-register (no shuffles, full-lane
// stores). Pipeline per tile: CP_WAIT -> sync -> convert (stage->fp16 A +
// fused h_sum) -> sync -> issue next cp.async -> MMA -> epilogue.
// smem: B[128][136] fp16 (34816) | A[64][136] fp16 (17408) | stage 32768
// ---------------------------------------------------------------------------
#define FSLOTS 74
__global__ void __launch_bounds__(256, 2) k_fmma(
    const float* __restrict__ h, const float* __restrict__ c_in,
    const float* __restrict__ f_input, const float* __restrict__ b_f,
    float* __restrict__ out)
{
    const int t    = blockIdx.x & 3;
    const int slot = blockIdx.x >> 2;
    const int cnt  = g_cnt[t];
    const int ntiles = (cnt + 7) >> 3;
    if (slot >= ntiles) return;

    extern __shared__ __align__(16) char sm[];
    __half* Bf  = (__half*)sm;                      // 34816
    __half* Af  = (__half*)(sm + 34816);            // 17408
    float*  stg = (float*)(sm + 34816 + 17408);     // 32768 (unpadded 64x128 f32)
    const uint32_t su = smem_to_u32(sm);
    const uint32_t bOff = su, aOff = su + 34816, sOff = su + 34816 + 17408;

    const int tid  = threadIdx.x;
    const int wid  = tid >> 5, lane = tid & 31;
    const int wn   = wid;                            // warp owns cols [wn*16, wn*16+16)
    const int l15 = lane & 15, lh = (lane >> 4) << 3;
    const int q = lane & 3, lr = lane >> 2;          // lr = local node
    const int* perm = g_perm[t];

    // ---- B load once (L2-hot), padded ----
    {
        const uint4* sh = (const uint4*)g_Bf[t];
        #pragma unroll
        for (int i = tid; i < 2048; i += 256) {
            int row = i >> 4, qq = i & 15;
            *(uint4*)(Bf + row * APAD + qq * 8) = sh[i];
        }
    }
    // bias preload (2 cols per thread per nt)
    float2 bfv[2];
    #pragma unroll
    for (int nt = 0; nt < 2; nt++)
        bfv[nt] = *(const float2*)(b_f + t * Hs + wn * 16 + nt * 8 + q * 2);

    // issue h tile -> stage: stage row r = k*8 + nl (child-major)
    auto issue_h = [&](int tl) {
        #pragma unroll
        for (int i = 0; i < 8; i++) {
            int o = (i * 256 + tid) * 16;
            int r = o >> 9;                     // row 0..63: nl = r&7, k = r>>3
            int node = perm[min(tl * 8 + (r & 7), cnt - 1)];
            const char* src = (const char*)h + (size_t)node * 4096 + (r >> 3) * 512 + (o & 511);
            CP_ASYNC16(sOff + o, src);
        }
    };

    issue_h(slot);
    CP_COMMIT();

    // convert-phase mapping: warp cnl handles node cnl, cols lane*4
    const int cnl = wid;
    const int ccol = lane * 4;

    for (int tile = slot; tile < ntiles; tile += FSLOTS) {
        CP_WAIT0();
        __syncthreads();   // stage ready; prior MMA done reading A; B on first iter

        // ---- convert: stage(f32) -> A(f16) rows k*8+cnl, fused h_sum ----
        {
            float4 v[Kc];
            #pragma unroll
            for (int k = 0; k < Kc; k++)
                v[k] = *(const float4*)(stg + (k * 8 + cnl) * Hs + ccol);
            float4 hs = v[0];
            #pragma unroll
            for (int k = 1; k < Kc; k++) {
                hs.x += v[k].x; hs.y += v[k].y; hs.z += v[k].z; hs.w += v[k].w;
            }
            #pragma unroll
            for (int k = 0; k < Kc; k++) {
                uint2 pk;
                pk.x = f2h2(v[k].x, v[k].y);
                pk.y = f2h2(v[k].z, v[k].w);
                *(uint2*)(Af + (k * 8 + cnl) * APAD + ccol) = pk;
            }
            const int n = perm[min(tile * 8 + cnl, cnt - 1)];
            *(float4*)(g_hsum + (size_t)n * Hs + ccol) = hs;
        }
        __syncthreads();   // A visible; stage free for refill

        int nxt = tile + FSLOTS;
        if (nxt < ntiles) { issue_h(nxt); }
        CP_COMMIT();

        // ---- single-pass fp16 MMA: mt=0..3 (M), nt=0..1 (N=16/warp) ----
        float acc[4][2][4];
        #pragma unroll
        for (int mt = 0; mt < 4; mt++)
            #pragma unroll
            for (int nt = 0; nt < 2; nt++)
                #pragma unroll
                for (int e = 0; e < 4; e++) acc[mt][nt][e] = 0.f;

        #pragma unroll
        for (int ks = 0; ks < 8; ks++) {
            uint32_t a[4][4];
            #pragma unroll
            for (int mt = 0; mt < 4; mt++)
                ldm_x4(a[mt], aOff + (((mt * 16 + l15) * APAD + ks * 16 + lh) << 1));
            uint32_t b[2][2];
            {
                uint32_t r[4];
                ldm_x4t(r, bOff + (((ks * 16 + l15) * APAD + wn * 16 + lh) << 1));
                b[0][0] = r[0]; b[0][1] = r[1];
                b[1][0] = r[2]; b[1][1] = r[3];
            }
            #pragma unroll
            for (int mt = 0; mt < 4; mt++)
                #pragma unroll
                for (int nt = 0; nt < 2; nt++)
                    mma16816h(acc[mt][nt], a[mt], b[nt]);
        }

        // ---- epilogue: in-register 8-child reduction, no shuffles ----
        // acc[mt][nt][0..1] = (node lr, k=2mt), acc[mt][nt][2..3] = (node lr, k=2mt+1)
        {
            const int na = perm[min(tile * 8 + lr, cnt - 1)];
            const int col0 = wn * 16 + q * 2;
            float2 f0 = *(const float2*)(f_input + (size_t)na * Hs + col0);
            float2 f1 = *(const float2*)(f_input + (size_t)na * Hs + col0 + 8);
            const float* crow = c_in + (size_t)na * (Kc * Hs);
            float s00 = 0.f, s01 = 0.f, s10 = 0.f, s11 = 0.f;
            #pragma unroll
            for (int mt = 0; mt < 4; mt++) {
                // batch the 4 c-loads for this mt (k = 2mt, 2mt+1; nt = 0,1)
                float2 cA0 = *(const float2*)(crow + (2 * mt) * Hs + col0);
                float2 cA1 = *(const float2*)(crow + (2 * mt) * Hs + col0 + 8);
                float2 cB0 = *(const float2*)(crow + (2 * mt + 1) * Hs + col0);
                float2 cB1 = *(const float2*)(crow + (2 * mt + 1) * Hs + col0 + 8);
                float x;
                x = acc[mt][0][0] + f0.x + bfv[0].x; s00 += cA0.x / (1.f + __expf(-x));
                x = acc[mt][0][1] + f0.y + bfv[0].y; s01 += cA0.y / (1.f + __expf(-x));
                x = acc[mt][0][2] + f0.x + bfv[0].x; s00 += cB0.x / (1.f + __expf(-x));
                x = acc[mt][0][3] + f0.y + bfv[0].y; s01 += cB0.y / (1.f + __expf(-x));
                x = acc[mt][1][0] + f1.x + bfv[1].x; s10 += cA1.x / (1.f + __expf(-x));
                x = acc[mt][1][1] + f1.y + bfv[1].y; s11 += cA1.y / (1.f + __expf(-x));
                x = acc[mt][1][2] + f1.x + bfv[1].x; s10 += cB1.x / (1.f + __expf(-x));
                x = acc[mt][1][3] + f1.y + bfv[1].y; s11 += cB1.y / (1.f + __expf(-x));
            }
            if (tile * 8 + lr < cnt) {
                float* orow = out + (size_t)na * (4 * Hs) + 3 * Hs;
                *(float2*)(orow + col0)     = make_float2(s00, s01);
                *(float2*)(orow + col0 + 8) = make_float2(s10, s11);
            }
        }
    }
}

// ---------------------------------------------------------------------------
// k_imma: R14 version (measured good). PERSISTENT per (type, jtile),
// cp.async-pipelined, 2 CTA/SM. B_iou[t][jt] single fp16 resident; h_sum
// tiles stream into double-buffered stage; A = hi+lo fp16 in-register.
// smem: B[128][136] fp16 (34816) | stage0 | stage1 (34816 each)
// ---------------------------------------------------------------------------
#define ISLOTS 24
__global__ void __launch_bounds__(256, 2) k_imma(
    const float* __restrict__ b_iou, float* __restrict__ out)
{
    const int grpid = blockIdx.x % 12;
    const int slot  = blockIdx.x / 12;
    const int t  = grpid & 3;
    const int jt = grpid >> 2;
    const int cnt = g_cnt[t];
    const int ntiles = (cnt + 63) >> 6;
    if (slot >= ntiles) return;

    extern __shared__ __align__(16) char sm[];
    __half* Bh = (__half*)sm;                       // 34816
    const uint32_t su = smem_to_u32(sm);
    const uint32_t bOff = su;

    const int tid = threadIdx.x;
    const int wid = tid >> 5, lane = tid & 31;
    const int wm = wid & 1, wn = wid >> 1;
    const int l15 = lane & 15, lh = (lane >> 4) << 3;
    const int q = lane & 3, lr = lane >> 2;
    const int fr = lane >> 2, fc = (lane & 3) * 2;
    const int* perm = g_perm[t];

    {
        const uint4* sh = (const uint4*)g_Bi[t][jt];
        #pragma unroll
        for (int i = tid; i < 2048; i += 256) {
            int row = i >> 4, qq = i & 15;
            *(uint4*)(Bh + row * APAD + qq * 8) = sh[i];
        }
    }
    float2 bv[4];
    #pragma unroll
    for (int nt = 0; nt < 4; nt++)
        bv[nt] = *(const float2*)(b_iou + (size_t)t * 3 * Hs + jt * Hs + wn * 32 + nt * 8 + q * 2);

    auto issue_hs = [&](int tl, uint32_t dstbase) {
        #pragma unroll
        for (int i = 0; i < 8; i++) {
            int o = (i * 256 + tid) * 16;
            int r = o >> 9;
            int node = perm[min(tl * 64 + r, cnt - 1)];
            const char* src = (const char*)g_hsum + (size_t)node * 512 + (o & 511);
            CP_ASYNC16(su + dstbase + r * (SPAD * 4) + (o & 511), src);
        }
    };

    issue_hs(slot, 34816);
    CP_COMMIT();

    int buf = 0;
    for (int tile = slot; tile < ntiles; tile += ISLOTS, buf ^= 1) {
        const float* stg = (const float*)(sm + 34816 + buf * 34816);
        CP_WAIT0();
        __syncthreads();

        int nxt = tile + ISLOTS;
        if (nxt < ntiles) issue_hs(nxt, 34816 + (buf ^ 1) * 34816);
        CP_COMMIT();

        float acc[2][4][4];
        #pragma unroll
        for (int mt = 0; mt < 2; mt++)
            #pragma unroll
            for (int nt = 0; nt < 4; nt++)
                #pragma unroll
                for (int e = 0; e < 4; e++) acc[mt][nt][e] = 0.f;

        #pragma unroll
        for (int ks = 0; ks < 8; ks++) {
            uint32_t ahi[2][4], alo[2][4];
            #pragma unroll
            for (int mt = 0; mt < 2; mt++) {
                const float* s0 = stg + (wm * 32 + mt * 16 + fr) * SPAD + ks * 16 + fc;
                float2 v;
                v = *(const float2*)(s0);                f2h2_split(v.x, v.y, ahi[mt][0], alo[mt][0]);
                v = *(const float2*)(s0 + 8 * SPAD);     f2h2_split(v.x, v.y, ahi[mt][1], alo[mt][1]);
                v = *(const float2*)(s0 + 8);            f2h2_split(v.x, v.y, ahi[mt][2], alo[mt][2]);
                v = *(const float2*)(s0 + 8 * SPAD + 8); f2h2_split(v.x, v.y, ahi[mt][3], alo[mt][3]);
            }
            uint32_t b[4][2];
            #pragma unroll
            for (int nb2 = 0; nb2 < 2; nb2++) {
                uint32_t r[4];
                ldm_x4t(r, bOff + (((ks * 16 + l15) * APAD + wn * 32 + nb2 * 16 + lh) << 1));
                b[nb2 * 2][0] = r[0]; b[nb2 * 2][1] = r[1];
                b[nb2 * 2 + 1][0] = r[2]; b[nb2 * 2 + 1][1] = r[3];
            }
            #pragma unroll
            for (int mt = 0; mt < 2; mt++)
                #pragma unroll
                for (int nt = 0; nt < 4; nt++) {
                    mma16816h(acc[mt][nt], ahi[mt], b[nt]);
                    mma16816h(acc[mt][nt], alo[mt], b[nt]);
                }
        }

        #pragma unroll
        for (int mt = 0; mt < 2; mt++) {
            #pragma unroll
            for (int half = 0; half < 2; half++) {
                const int row = wm * 32 + mt * 16 + lr + half * 8;
                if (tile * 64 + row < cnt) {
                    float* orow = out + (size_t)perm[tile * 64 + row] * (4 * Hs) + jt * Hs;
                    #pragma unroll
                    for (int nt = 0; nt < 4; nt++) {
                        const int col = wn * 32 + nt * 8 + q * 2;
                        *(float2*)(orow + col) = make_float2(
                            acc[mt][nt][half * 2 + 0] + bv[nt].x,
                            acc[mt][nt][half * 2 + 1] + bv[nt].y);
                    }
                }
            }
        }
    }
}

// ---------------------------------------------------------------------------
extern "C" void kernel_launch(void* const* d_in, const int* in_sizes, int n_in,
                              void* d_out, int out_size)
{
    const float* h       = (const float*)d_in[0];
    const float* c       = (const float*)d_in[1];
    const float* f_input = (const float*)d_in[2];
    const int*   type_id = (const int*)  d_in[3];
    const float* U_iou   = (const float*)d_in[4];
    const float* b_iou   = (const float*)d_in[5];
    const float* U_f     = (const float*)d_in[6];
    const float* b_f     = (const float*)d_in[7];
    float*       out     = (float*)d_out;

    const int smemF = 34816 + 17408 + 32768;    // 84992 -> 2 CTAs/SM
    const int smemI = 34816 * 3;                // 104448 -> 2 CTAs/SM
    cudaFuncSetAttribute(k_fmma, cudaFuncAttributeMaxDynamicSharedMemorySize, smemF);
    cudaFuncSetAttribute(k_imma, cudaFuncAttributeMaxDynamicSharedMemorySize, smemI);

    k_zero<<<1, 32>>>();
    k_bucket<<<Nn / 256, 256>>>(type_id);
    k_prepw<<<1024, 256>>>(U_iou, U_f);

    k_fmma<<<4 * FSLOTS, 256, smemF>>>(h, c, f_input, b_f, out);
    k_imma<<<12 * ISLOTS, 256, smemI>>>(b_iou, out);
}